// round 2
// baseline (speedup 1.0000x reference)
#include <cuda_runtime.h>
#include <math.h>

// Problem constants (fixed shapes from reference setup_inputs)
#define B_      4
#define C_      256
#define P_      65536          // H*W = 256*256
#define NSEG    32             // object ids 1..32
#define PT      512            // pixels per tile
#define TILES_PER_B (P_ / PT)  // 128
#define NBLK1   (B_ * TILES_PER_B)  // 512 blocks
#define THREADS1 128
#define UNROLL_C 4

// Per-tile partial maxima, laid out [b][seg][tile][c] so phase 2 reads are
// fully contiguous per (b,seg): 512*32*256 floats = 16 MB
__device__ float g_scratch[(size_t)B_ * NSEG * TILES_PER_B * C_];

// ---------------------------------------------------------------------------
// Phase 1: per-tile segmented max over pixels, all 256 channels per block.
// accum stored as int bit-patterns of non-negative floats (clamp-at-0 is free:
// init 0, and for non-negative floats int compare == float compare).
// v <= 0 can never beat the 0 init -> skip shared check entirely (~50% of data).
// ---------------------------------------------------------------------------
__global__ __launch_bounds__(THREADS1)
void seg_pool_kernel(const float* __restrict__ enc, const int* __restrict__ masks) {
    __shared__ int accum[C_ * 33];   // [c][id 0..32], stride 33 spreads banks

    const int blk  = blockIdx.x;
    const int b    = blk / TILES_PER_B;
    const int tile = blk % TILES_PER_B;
    const int tid  = threadIdx.x;

    // zero accumulator
    #pragma unroll
    for (int i = tid; i < C_ * 33; i += THREADS1) accum[i] = 0;

    // load 4 mask ids per thread, once, into registers (reused for all channels)
    const int pbase = tile * PT;
    const int4 idv = reinterpret_cast<const int4*>(masks + (size_t)b * P_ + pbase)[tid];
    const int id0 = idv.x, id1 = idv.y, id2 = idv.z, id3 = idv.w;

    __syncthreads();

    const float* encb = enc + (size_t)b * C_ * P_ + pbase;

    for (int c0 = 0; c0 < C_; c0 += UNROLL_C) {
        float4 v[UNROLL_C];
        #pragma unroll
        for (int u = 0; u < UNROLL_C; u++)
            v[u] = __ldcs(reinterpret_cast<const float4*>(encb + (size_t)(c0 + u) * P_) + tid);

        #pragma unroll
        for (int u = 0; u < UNROLL_C; u++) {
            const int base = (c0 + u) * 33;
            int iv;
            iv = __float_as_int(v[u].x);
            if (iv > 0 && iv > accum[base + id0]) atomicMax(&accum[base + id0], iv);
            iv = __float_as_int(v[u].y);
            if (iv > 0 && iv > accum[base + id1]) atomicMax(&accum[base + id1], iv);
            iv = __float_as_int(v[u].z);
            if (iv > 0 && iv > accum[base + id2]) atomicMax(&accum[base + id2], iv);
            iv = __float_as_int(v[u].w);
            if (iv > 0 && iv > accum[base + id3]) atomicMax(&accum[base + id3], iv);
        }
    }
    __syncthreads();

    // flush to [b][seg][tile][c] (drop id 0 = background); shared reads
    // accum[c*33 + s + 1] with consecutive c -> distinct banks.
    #pragma unroll
    for (int i = tid; i < NSEG * C_; i += THREADS1) {
        const int s = i >> 8;        // 0..31
        const int c = i & 255;       // 0..255
        g_scratch[(((size_t)b * NSEG + s) * TILES_PER_B + tile) * C_ + c] =
            __int_as_float(accum[c * 33 + s + 1]);  // already >= 0
    }
}

// ---------------------------------------------------------------------------
// Phase 2: reduce partial maxima across tiles, then MLP + sigmoid.
// One block per (batch, object). 1024 threads: (channel, quarter-of-tiles).
// Each block reads a contiguous 128 KB span; 32 loads in flight per thread.
// ---------------------------------------------------------------------------
__global__ __launch_bounds__(1024)
void reduce_mlp_kernel(const float* __restrict__ w1, const float* __restrict__ b1,
                       const float* __restrict__ w2, const float* __restrict__ b2,
                       float* __restrict__ out) {
    __shared__ float part[4][C_];
    __shared__ float pooled[C_];
    __shared__ float h[C_ / 2];

    const int blk = blockIdx.x;      // b*NSEG + n
    const int b   = blk / NSEG;
    const int n   = blk % NSEG;
    const int tid = threadIdx.x;     // 0..1023
    const int c     = tid & 255;
    const int chunk = tid >> 8;      // 0..3, each owns 32 tiles

    const float* base = g_scratch
        + (((size_t)b * NSEG + n) * TILES_PER_B + (size_t)chunk * 32) * C_ + c;
    float m = 0.0f;
    #pragma unroll
    for (int t = 0; t < 32; t++)
        m = fmaxf(m, base[(size_t)t * C_]);
    part[chunk][c] = m;
    __syncthreads();

    if (tid < C_) {
        pooled[tid] = fmaxf(fmaxf(part[0][tid], part[1][tid]),
                            fmaxf(part[2][tid], part[3][tid]));
    }
    __syncthreads();

    // h = pooled @ w1 + b1   (w1: [256,128] row-major -> coalesced over tid)
    if (tid < 128) {
        float acc = b1[tid];
        #pragma unroll 8
        for (int cc = 0; cc < C_; cc++)
            acc = fmaf(pooled[cc], w1[cc * 128 + tid], acc);
        h[tid] = acc;
    }
    __syncthreads();

    // bbox = sigmoid(h @ w2 + b2)   (w2: [128,4])
    if (tid < 4) {
        float acc = b2[tid];
        #pragma unroll 8
        for (int j = 0; j < 128; j++)
            acc = fmaf(h[j], w2[j * 4 + tid], acc);
        out[blk * 4 + tid] = 1.0f / (1.0f + expf(-acc));
    }
}

// ---------------------------------------------------------------------------
extern "C" void kernel_launch(void* const* d_in, const int* in_sizes, int n_in,
                              void* d_out, int out_size) {
    const float* enc   = (const float*)d_in[0];  // [4,256,256,256] f32
    const float* w1    = (const float*)d_in[1];  // [256,128]
    const float* b1    = (const float*)d_in[2];  // [128]
    const float* w2    = (const float*)d_in[3];  // [128,4]
    const float* b2    = (const float*)d_in[4];  // [4]
    const int*   masks = (const int*)d_in[5];    // [4,1,256,256] i32

    seg_pool_kernel<<<NBLK1, THREADS1>>>(enc, masks);
    reduce_mlp_kernel<<<B_ * NSEG, 1024>>>(w1, b1, w2, b2, (float*)d_out);
}

// round 3
// speedup vs baseline: 1.2693x; 1.2693x over previous
#include <cuda_runtime.h>
#include <math.h>

// Problem constants (fixed shapes from reference setup_inputs)
#define B_      4
#define C_      256
#define P_      65536          // H*W = 256*256
#define NSEG    32             // object ids 1..32
#define PT      512            // pixels per tile
#define TILES_PER_B (P_ / PT)  // 128
#define NBLK1   (B_ * TILES_PER_B)  // 512 blocks
#define THREADS1 128
#define UNROLL_C 8

// Per-tile partial maxima [b][seg][tile][c]: 4*32*128*256 floats = 16 MB
__device__ float g_scratch[(size_t)B_ * NSEG * TILES_PER_B * C_];

// ---------------------------------------------------------------------------
// Phase 1: per-tile segmented max over pixels, all 256 channels per block.
// accum holds int bit-patterns of non-negative floats (init 0 == clamp at 0;
// for non-negative floats int compare == float compare). Since accum >= 0,
// "iv > accum" already rejects every non-positive value — no extra filter.
// ---------------------------------------------------------------------------
__global__ __launch_bounds__(THREADS1)
void seg_pool_kernel(const float* __restrict__ enc, const int* __restrict__ masks) {
    __shared__ int accum[C_ * 33];   // [c][id 0..32], stride 33 spreads banks

    const int blk  = blockIdx.x;
    const int b    = blk / TILES_PER_B;
    const int tile = blk % TILES_PER_B;
    const int tid  = threadIdx.x;

    #pragma unroll
    for (int i = tid; i < C_ * 33; i += THREADS1) accum[i] = 0;

    // 4 mask ids per thread, loaded once, reused for all 256 channels
    const int pbase = tile * PT;
    const int4 idv = reinterpret_cast<const int4*>(masks + (size_t)b * P_ + pbase)[tid];
    const int id0 = idv.x, id1 = idv.y, id2 = idv.z, id3 = idv.w;

    __syncthreads();

    const float* encb = enc + (size_t)b * C_ * P_ + pbase;

    for (int c0 = 0; c0 < C_; c0 += UNROLL_C) {
        float4 v[UNROLL_C];
        #pragma unroll
        for (int u = 0; u < UNROLL_C; u++)   // 8 LDG.128 front-batched
            v[u] = reinterpret_cast<const float4*>(encb + (size_t)(c0 + u) * P_)[tid];

        #pragma unroll
        for (int u = 0; u < UNROLL_C; u++) {
            const int base = (c0 + u) * 33;
            int iv;
            iv = __float_as_int(v[u].x); if (iv > accum[base + id0]) atomicMax(&accum[base + id0], iv);
            iv = __float_as_int(v[u].y); if (iv > accum[base + id1]) atomicMax(&accum[base + id1], iv);
            iv = __float_as_int(v[u].z); if (iv > accum[base + id2]) atomicMax(&accum[base + id2], iv);
            iv = __float_as_int(v[u].w); if (iv > accum[base + id3]) atomicMax(&accum[base + id3], iv);
        }
    }
    __syncthreads();

    // flush to [b][seg][tile][c] (drop id 0 = background)
    #pragma unroll
    for (int i = tid; i < NSEG * C_; i += THREADS1) {
        const int s = i >> 8;        // 0..31
        const int c = i & 255;       // 0..255
        g_scratch[(((size_t)b * NSEG + s) * TILES_PER_B + tile) * C_ + c] =
            __int_as_float(accum[c * 33 + s + 1]);  // already >= 0
    }
}

// ---------------------------------------------------------------------------
// Phase 2: reduce 128 tile-partials per (b,seg), then MLP + sigmoid.
// One block per (b,seg), 1024 threads = 16 tile-chunks x 64 float4-columns.
// Each thread issues 8 independent LDG.128 (explicit array -> front-batched).
// ---------------------------------------------------------------------------
__global__ __launch_bounds__(1024)
void reduce_mlp_kernel(const float* __restrict__ w1, const float* __restrict__ b1,
                       const float* __restrict__ w2, const float* __restrict__ b2,
                       float* __restrict__ out) {
    __shared__ float part[16][C_];   // 16 KB
    __shared__ float h[C_ / 2];

    const int blk = blockIdx.x;      // b*NSEG + n
    const int b   = blk / NSEG;
    const int n   = blk % NSEG;
    const int tid = threadIdx.x;
    const int c4    = (tid & 63) * 4;   // float4 column
    const int chunk = tid >> 6;         // 0..15, each owns 8 tiles

    const float* base = g_scratch
        + (((size_t)b * NSEG + n) * TILES_PER_B + (size_t)chunk * 8) * C_ + c4;

    float4 v[8];
    #pragma unroll
    for (int t = 0; t < 8; t++)          // 8 LDG.128 in flight
        v[t] = *reinterpret_cast<const float4*>(base + (size_t)t * C_);

    float4 m = v[0];
    #pragma unroll
    for (int t = 1; t < 8; t++) {
        m.x = fmaxf(m.x, v[t].x); m.y = fmaxf(m.y, v[t].y);
        m.z = fmaxf(m.z, v[t].z); m.w = fmaxf(m.w, v[t].w);
    }
    *reinterpret_cast<float4*>(&part[chunk][c4]) = m;
    __syncthreads();

    // tree-reduce 16 chunks -> chunk 0
    #pragma unroll
    for (int stride = 8; stride >= 1; stride >>= 1) {
        if (chunk < stride) {
            float4 a = *reinterpret_cast<const float4*>(&part[chunk][c4]);
            float4 bb = *reinterpret_cast<const float4*>(&part[chunk + stride][c4]);
            a.x = fmaxf(a.x, bb.x); a.y = fmaxf(a.y, bb.y);
            a.z = fmaxf(a.z, bb.z); a.w = fmaxf(a.w, bb.w);
            *reinterpret_cast<float4*>(&part[chunk][c4]) = a;
        }
        __syncthreads();
    }
    // part[0][0..255] == pooled

    // h = pooled @ w1 + b1   (w1: [256,128] row-major -> coalesced over tid)
    if (tid < 128) {
        float acc = b1[tid];
        #pragma unroll 8
        for (int cc = 0; cc < C_; cc++)
            acc = fmaf(part[0][cc], w1[cc * 128 + tid], acc);
        h[tid] = acc;
    }
    __syncthreads();

    // bbox = sigmoid(h @ w2 + b2)   (w2: [128,4])
    if (tid < 4) {
        float acc = b2[tid];
        #pragma unroll 8
        for (int j = 0; j < 128; j++)
            acc = fmaf(h[j], w2[j * 4 + tid], acc);
        out[blk * 4 + tid] = 1.0f / (1.0f + expf(-acc));
    }
}

// ---------------------------------------------------------------------------
extern "C" void kernel_launch(void* const* d_in, const int* in_sizes, int n_in,
                              void* d_out, int out_size) {
    const float* enc   = (const float*)d_in[0];  // [4,256,256,256] f32
    const float* w1    = (const float*)d_in[1];  // [256,128]
    const float* b1    = (const float*)d_in[2];  // [128]
    const float* w2    = (const float*)d_in[3];  // [128,4]
    const float* b2    = (const float*)d_in[4];  // [4]
    const int*   masks = (const int*)d_in[5];    // [4,1,256,256] i32

    seg_pool_kernel<<<NBLK1, THREADS1>>>(enc, masks);
    reduce_mlp_kernel<<<B_ * NSEG, 1024>>>(w1, b1, w2, b2, (float*)d_out);
}

// round 4
// speedup vs baseline: 1.3571x; 1.0691x over previous
#include <cuda_runtime.h>
#include <math.h>

// Problem constants (fixed shapes from reference setup_inputs)
#define B_      4
#define C_      256
#define P_      65536          // H*W = 256*256
#define NSEG    32             // object ids 1..32
#define PT      512            // pixels per tile
#define TILES_PER_B (P_ / PT)  // 128
#define NBLK1   (B_ * TILES_PER_B)  // 512 blocks
#define THREADS1 128
#define NQ      (C_ / 4)       // 64 channel-quads

// Per-tile partial maxima [b][seg][tile][c]: 4*32*128*256 floats = 16 MB
__device__ float g_scratch[(size_t)B_ * NSEG * TILES_PER_B * C_];

// ---------------------------------------------------------------------------
// Phase 1: per-tile segmented max, accumulator laid out [cquad][id][4ch] so a
// single LDS.128 snapshots 4 channels' current maxima for one id. Values are
// non-negative float bit-patterns (init 0 == clamp at 0; int cmp == float cmp).
// Stale snapshots are safe: accum grows monotonically, so a stale read can only
// trigger a redundant atomicMax, never skip a needed one.
// ---------------------------------------------------------------------------
__global__ __launch_bounds__(THREADS1)
void seg_pool_kernel(const float* __restrict__ enc, const int* __restrict__ masks) {
    __shared__ int4 accum4[NQ * 33];            // 64*33*16 B = 33 KB
    int* accum = reinterpret_cast<int*>(accum4);

    const int blk  = blockIdx.x;
    const int b    = blk / TILES_PER_B;
    const int tile = blk % TILES_PER_B;
    const int tid  = threadIdx.x;

    #pragma unroll
    for (int i = tid; i < NQ * 33 * 4; i += THREADS1) accum[i] = 0;

    // 4 mask ids per thread, loaded once, reused for all 256 channels
    const int pbase = tile * PT;
    const int4 idv = reinterpret_cast<const int4*>(masks + (size_t)b * P_ + pbase)[tid];
    const int id0 = idv.x, id1 = idv.y, id2 = idv.z, id3 = idv.w;

    __syncthreads();

    const float* encb = enc + (size_t)b * C_ * P_ + pbase;

    for (int c0 = 0; c0 < C_; c0 += 8) {
        float4 v[8];
        #pragma unroll
        for (int u = 0; u < 8; u++)              // 8 LDG.128 front-batched
            v[u] = reinterpret_cast<const float4*>(encb + (size_t)(c0 + u) * P_)[tid];

        #pragma unroll
        for (int q = 0; q < 2; q++) {            // two channel-quads per batch
            const int cq = (c0 >> 2) + q;
            const float4 w0 = v[4*q + 0], w1v = v[4*q + 1],
                         w2v = v[4*q + 2], w3 = v[4*q + 3];

            #define CHECK_PIXEL(IDX, COMP)                                          \
            {                                                                       \
                const int4 cur = accum4[cq * 33 + IDX];                             \
                const int base = (cq * 33 + IDX) * 4;                               \
                int a;                                                              \
                a = __float_as_int(w0.COMP);  if (a > cur.x) atomicMax(&accum[base + 0], a); \
                a = __float_as_int(w1v.COMP); if (a > cur.y) atomicMax(&accum[base + 1], a); \
                a = __float_as_int(w2v.COMP); if (a > cur.z) atomicMax(&accum[base + 2], a); \
                a = __float_as_int(w3.COMP);  if (a > cur.w) atomicMax(&accum[base + 3], a); \
            }
            CHECK_PIXEL(id0, x)
            CHECK_PIXEL(id1, y)
            CHECK_PIXEL(id2, z)
            CHECK_PIXEL(id3, w)
            #undef CHECK_PIXEL
        }
    }
    __syncthreads();

    // flush to [b][seg][tile][c] (drop id 0 = background)
    #pragma unroll
    for (int i = tid; i < NSEG * C_; i += THREADS1) {
        const int s = i >> 8;        // 0..31
        const int c = i & 255;       // 0..255
        g_scratch[(((size_t)b * NSEG + s) * TILES_PER_B + tile) * C_ + c] =
            __int_as_float(accum[((c >> 2) * 33 + s + 1) * 4 + (c & 3)]);
    }
}

// ---------------------------------------------------------------------------
// Phase 2: reduce 128 tile-partials per (b,seg), then the COLLAPSED MLP:
// no activation between layers, so bbox = sigmoid(pooled @ (w1@w2) + b1@w2 + b2).
// Each thread owns one (c,o) entry of Wf = w1@w2 (128-dot, L2-hot, overlaps the
// scratch loads), then the tail is one multiply + a 4-warp tree sum.
// ---------------------------------------------------------------------------
__global__ __launch_bounds__(1024)
void reduce_mlp_kernel(const float* __restrict__ w1, const float* __restrict__ b1,
                       const float* __restrict__ w2, const float* __restrict__ b2,
                       float* __restrict__ out) {
    __shared__ float part[16][C_];   // 16 KB
    __shared__ float mlp[4][C_];     // 4 KB: per-output partial products

    const int blk = blockIdx.x;      // b*NSEG + n
    const int b   = blk / NSEG;
    const int n   = blk % NSEG;
    const int tid = threadIdx.x;
    const int c4    = (tid & 63) * 4;   // float4 column for the max phase
    const int chunk = tid >> 6;         // 0..15, each owns 8 tiles
    const int c     = tid >> 2;         // 0..255: Wf row
    const int o     = tid & 3;          // 0..3:   Wf col

    // --- fused-weight entry Wf[c][o] = sum_j w1[c][j] * w2[j][o] ---
    float wf = 0.0f;
    {
        const float* w1r = w1 + c * 128;
        #pragma unroll 8
        for (int j = 0; j < 128; j++)
            wf = fmaf(w1r[j], w2[j * 4 + o], wf);
    }

    // --- max over 128 tiles (8 LDG.128 in flight per thread) ---
    const float* base = g_scratch
        + (((size_t)b * NSEG + n) * TILES_PER_B + (size_t)chunk * 8) * C_ + c4;
    float4 v[8];
    #pragma unroll
    for (int t = 0; t < 8; t++)
        v[t] = *reinterpret_cast<const float4*>(base + (size_t)t * C_);
    float4 m = v[0];
    #pragma unroll
    for (int t = 1; t < 8; t++) {
        m.x = fmaxf(m.x, v[t].x); m.y = fmaxf(m.y, v[t].y);
        m.z = fmaxf(m.z, v[t].z); m.w = fmaxf(m.w, v[t].w);
    }
    *reinterpret_cast<float4*>(&part[chunk][c4]) = m;
    __syncthreads();

    #pragma unroll
    for (int stride = 8; stride >= 1; stride >>= 1) {
        if (chunk < stride) {
            float4 a = *reinterpret_cast<const float4*>(&part[chunk][c4]);
            float4 bb = *reinterpret_cast<const float4*>(&part[chunk + stride][c4]);
            a.x = fmaxf(a.x, bb.x); a.y = fmaxf(a.y, bb.y);
            a.z = fmaxf(a.z, bb.z); a.w = fmaxf(a.w, bb.w);
            *reinterpret_cast<float4*>(&part[chunk][c4]) = a;
        }
        __syncthreads();
    }
    // part[0][0..255] == pooled

    // --- per-(c,o) contribution + bias term (b1@w2 folded in for c<128) ---
    float contrib = part[0][c] * wf;
    if (c < 128) contrib = fmaf(b1[c], w2[c * 4 + o], contrib);
    mlp[o][c] = contrib;
    __syncthreads();

    // --- 4 warps: warp w sums mlp[w][0..255], lane 0 writes sigmoid ---
    const int wid = tid >> 5, lane = tid & 31;
    if (wid < 4) {
        float s = 0.0f;
        #pragma unroll
        for (int k = 0; k < 8; k++) s += mlp[wid][lane + 32 * k];
        #pragma unroll
        for (int d = 16; d >= 1; d >>= 1) s += __shfl_xor_sync(0xffffffffu, s, d);
        if (lane == 0)
            out[blk * 4 + wid] = 1.0f / (1.0f + expf(-(s + b2[wid])));
    }
}

// ---------------------------------------------------------------------------
extern "C" void kernel_launch(void* const* d_in, const int* in_sizes, int n_in,
                              void* d_out, int out_size) {
    const float* enc   = (const float*)d_in[0];  // [4,256,256,256] f32
    const float* w1    = (const float*)d_in[1];  // [256,128]
    const float* b1    = (const float*)d_in[2];  // [128]
    const float* w2    = (const float*)d_in[3];  // [128,4]
    const float* b2    = (const float*)d_in[4];  // [4]
    const int*   masks = (const int*)d_in[5];    // [4,1,256,256] i32

    seg_pool_kernel<<<NBLK1, THREADS1>>>(enc, masks);
    reduce_mlp_kernel<<<B_ * NSEG, 1024>>>(w1, b1, w2, b2, (float*)d_out);
}

// round 5
// speedup vs baseline: 1.8369x; 1.3535x over previous
#include <cuda_runtime.h>
#include <math.h>

// Problem constants (fixed shapes from reference setup_inputs)
#define B_      4
#define C_      256
#define P_      65536          // H*W = 256*256
#define NSEG    32             // object ids 1..32
#define PT      512            // pixels per tile
#define TILES_PER_B (P_ / PT)  // 128
#define NBLK1   (B_ * TILES_PER_B)  // 512 blocks
#define THREADS1 128
#define NQ      (C_ / 4)       // 64 channel-quads

// Per-tile partial maxima [b][seg][tile][c]: 4*32*128*256 floats = 16 MB
__device__ float g_scratch[(size_t)B_ * NSEG * TILES_PER_B * C_];
// Fused MLP weight Wf = w1@w2 [256][4] and bias = b2 + b1@w2 [4]
__device__ float g_wf[C_ * 4];
__device__ float g_bias[4];

// ---------------------------------------------------------------------------
// Precompute (once): Wf[c][o] = sum_j w1[c][j]*w2[j][o];  bias[o] = b2 + b1@w2
// ---------------------------------------------------------------------------
__global__ __launch_bounds__(128)
void wf_kernel(const float* __restrict__ w1, const float* __restrict__ b1,
               const float* __restrict__ w2, const float* __restrict__ b2) {
    const int t = blockIdx.x * 128 + threadIdx.x;   // 0..1023
    const int c = t >> 2, o = t & 3;
    float acc = 0.0f;
    const float* w1r = w1 + c * 128;
    #pragma unroll 16
    for (int j = 0; j < 128; j++)
        acc = fmaf(w1r[j], w2[j * 4 + o], acc);
    g_wf[t] = acc;
    if (t < 4) {
        float bb = b2[t];
        #pragma unroll 16
        for (int j = 0; j < 128; j++)
            bb = fmaf(b1[j], w2[j * 4 + t], bb);
        g_bias[t] = bb;
    }
}

// ---------------------------------------------------------------------------
// Phase 1: per-tile segmented max, accumulator [cquad][id][4ch]; one LDS.128
// snapshots 4 channels' maxima for a pixel's id. Non-negative float bits
// (init 0 == clamp at 0; int cmp == float cmp). Stale snapshots safe (monotone).
// Software-pipelined: next 8-channel batch loads issue before current batch's
// shared-memory work, keeping DRAM latency hidden.
// ---------------------------------------------------------------------------
__global__ __launch_bounds__(THREADS1)
void seg_pool_kernel(const float* __restrict__ enc, const int* __restrict__ masks) {
    __shared__ int4 accum4[NQ * 33];            // 33 KB
    int* accum = reinterpret_cast<int*>(accum4);

    const int blk  = blockIdx.x;
    const int b    = blk / TILES_PER_B;
    const int tile = blk % TILES_PER_B;
    const int tid  = threadIdx.x;

    #pragma unroll
    for (int i = tid; i < NQ * 33 * 4; i += THREADS1) accum[i] = 0;

    const int pbase = tile * PT;
    const int4 idv = reinterpret_cast<const int4*>(masks + (size_t)b * P_ + pbase)[tid];
    const int id0 = idv.x, id1 = idv.y, id2 = idv.z, id3 = idv.w;

    __syncthreads();

    const float* encb = enc + (size_t)b * C_ * P_ + pbase;

    #define LOADV(DST, CBASE)                                                   \
        _Pragma("unroll")                                                       \
        for (int u = 0; u < 8; u++)                                             \
            DST[u] = reinterpret_cast<const float4*>(encb + (size_t)((CBASE) + u) * P_)[tid];

    #define PROCESS(SRC, CBASE)                                                 \
        _Pragma("unroll")                                                       \
        for (int q = 0; q < 2; q++) {                                           \
            const int cq = ((CBASE) >> 2) + q;                                  \
            const float4 w0 = SRC[4*q + 0], w1v = SRC[4*q + 1],                 \
                         w2v = SRC[4*q + 2], w3 = SRC[4*q + 3];                 \
            const int rowb = cq * 33;                                           \
            {                                                                   \
                const int4 cur = accum4[rowb + id0];                            \
                const int base = (rowb + id0) * 4; int a;                       \
                a = __float_as_int(w0.x);  if (a > cur.x) atomicMax(&accum[base+0], a); \
                a = __float_as_int(w1v.x); if (a > cur.y) atomicMax(&accum[base+1], a); \
                a = __float_as_int(w2v.x); if (a > cur.z) atomicMax(&accum[base+2], a); \
                a = __float_as_int(w3.x);  if (a > cur.w) atomicMax(&accum[base+3], a); \
            }                                                                   \
            {                                                                   \
                const int4 cur = accum4[rowb + id1];                            \
                const int base = (rowb + id1) * 4; int a;                       \
                a = __float_as_int(w0.y);  if (a > cur.x) atomicMax(&accum[base+0], a); \
                a = __float_as_int(w1v.y); if (a > cur.y) atomicMax(&accum[base+1], a); \
                a = __float_as_int(w2v.y); if (a > cur.z) atomicMax(&accum[base+2], a); \
                a = __float_as_int(w3.y);  if (a > cur.w) atomicMax(&accum[base+3], a); \
            }                                                                   \
            {                                                                   \
                const int4 cur = accum4[rowb + id2];                            \
                const int base = (rowb + id2) * 4; int a;                       \
                a = __float_as_int(w0.z);  if (a > cur.x) atomicMax(&accum[base+0], a); \
                a = __float_as_int(w1v.z); if (a > cur.y) atomicMax(&accum[base+1], a); \
                a = __float_as_int(w2v.z); if (a > cur.z) atomicMax(&accum[base+2], a); \
                a = __float_as_int(w3.z);  if (a > cur.w) atomicMax(&accum[base+3], a); \
            }                                                                   \
            {                                                                   \
                const int4 cur = accum4[rowb + id3];                            \
                const int base = (rowb + id3) * 4; int a;                       \
                a = __float_as_int(w0.w);  if (a > cur.x) atomicMax(&accum[base+0], a); \
                a = __float_as_int(w1v.w); if (a > cur.y) atomicMax(&accum[base+1], a); \
                a = __float_as_int(w2v.w); if (a > cur.z) atomicMax(&accum[base+2], a); \
                a = __float_as_int(w3.w);  if (a > cur.w) atomicMax(&accum[base+3], a); \
            }                                                                   \
        }

    float4 va[8], vb[8];
    LOADV(va, 0)
    #pragma unroll 1
    for (int c0 = 0; c0 < C_; c0 += 16) {
        LOADV(vb, c0 + 8)
        PROCESS(va, c0)
        if (c0 + 16 < C_) { LOADV(va, c0 + 16) }
        PROCESS(vb, c0 + 8)
    }
    #undef LOADV
    #undef PROCESS

    __syncthreads();

    // flush to [b][seg][tile][c] (drop id 0 = background)
    #pragma unroll
    for (int i = tid; i < NSEG * C_; i += THREADS1) {
        const int s = i >> 8;
        const int c = i & 255;
        g_scratch[(((size_t)b * NSEG + s) * TILES_PER_B + tile) * C_ + c] =
            __int_as_float(accum[((c >> 2) * 33 + s + 1) * 4 + (c & 3)]);
    }
}

// ---------------------------------------------------------------------------
// Phase 2: max over 128 tile-partials per (b,seg), then one multiply by the
// precomputed fused weight + 4-warp tree sum + sigmoid. Pure bandwidth.
// ---------------------------------------------------------------------------
__global__ __launch_bounds__(1024)
void reduce_mlp_kernel(float* __restrict__ out) {
    __shared__ float part[16][C_];   // 16 KB
    __shared__ float mlp[4][C_];     // 4 KB

    const int blk = blockIdx.x;      // b*NSEG + n
    const int b   = blk / NSEG;
    const int n   = blk % NSEG;
    const int tid = threadIdx.x;
    const int c4    = (tid & 63) * 4;
    const int chunk = tid >> 6;         // 0..15, each owns 8 tiles
    const int c     = tid >> 2;         // 0..255
    const int o     = tid & 3;          // 0..3

    const float wf = g_wf[tid];         // Wf[c][o], coalesced

    const float* base = g_scratch
        + (((size_t)b * NSEG + n) * TILES_PER_B + (size_t)chunk * 8) * C_ + c4;
    float4 v[8];
    #pragma unroll
    for (int t = 0; t < 8; t++)
        v[t] = *reinterpret_cast<const float4*>(base + (size_t)t * C_);
    float4 m = v[0];
    #pragma unroll
    for (int t = 1; t < 8; t++) {
        m.x = fmaxf(m.x, v[t].x); m.y = fmaxf(m.y, v[t].y);
        m.z = fmaxf(m.z, v[t].z); m.w = fmaxf(m.w, v[t].w);
    }
    *reinterpret_cast<float4*>(&part[chunk][c4]) = m;
    __syncthreads();

    #pragma unroll
    for (int stride = 8; stride >= 1; stride >>= 1) {
        if (chunk < stride) {
            float4 a = *reinterpret_cast<const float4*>(&part[chunk][c4]);
            float4 bb = *reinterpret_cast<const float4*>(&part[chunk + stride][c4]);
            a.x = fmaxf(a.x, bb.x); a.y = fmaxf(a.y, bb.y);
            a.z = fmaxf(a.z, bb.z); a.w = fmaxf(a.w, bb.w);
            *reinterpret_cast<float4*>(&part[chunk][c4]) = a;
        }
        __syncthreads();
    }
    // part[0][0..255] == pooled

    mlp[o][c] = part[0][c] * wf;
    __syncthreads();

    const int wid = tid >> 5, lane = tid & 31;
    if (wid < 4) {
        float s = 0.0f;
        #pragma unroll
        for (int k = 0; k < 8; k++) s += mlp[wid][lane + 32 * k];
        #pragma unroll
        for (int d = 16; d >= 1; d >>= 1) s += __shfl_xor_sync(0xffffffffu, s, d);
        if (lane == 0)
            out[blk * 4 + wid] = 1.0f / (1.0f + expf(-(s + g_bias[wid])));
    }
}

// ---------------------------------------------------------------------------
extern "C" void kernel_launch(void* const* d_in, const int* in_sizes, int n_in,
                              void* d_out, int out_size) {
    const float* enc   = (const float*)d_in[0];  // [4,256,256,256] f32
    const float* w1    = (const float*)d_in[1];  // [256,128]
    const float* b1    = (const float*)d_in[2];  // [128]
    const float* w2    = (const float*)d_in[3];  // [128,4]
    const float* b2    = (const float*)d_in[4];  // [4]
    const int*   masks = (const int*)d_in[5];    // [4,1,256,256] i32

    wf_kernel<<<8, 128>>>(w1, b1, w2, b2);
    seg_pool_kernel<<<NBLK1, THREADS1>>>(enc, masks);
    reduce_mlp_kernel<<<B_ * NSEG, 1024>>>((float*)d_out);
}

// round 6
// speedup vs baseline: 2.2403x; 1.2196x over previous
#include <cuda_runtime.h>
#include <math.h>

// Problem constants (fixed shapes from reference setup_inputs)
#define B_      4
#define C_      256
#define P_      65536          // H*W = 256*256
#define NSEG    32             // object ids 1..32
#define PT      1024           // pixels per tile
#define TILES_PER_B (P_ / PT)  // 64
#define NBLK1   (B_ * TILES_PER_B)  // 256 blocks
#define THREADS1 256
#define NQ      (C_ / 4)       // 64 channel-quads

// Per-tile partial maxima [b][seg][tile][c]: 4*32*64*256 floats = 8 MB
__device__ float g_scratch[(size_t)B_ * NSEG * TILES_PER_B * C_];
// Fused MLP weight Wf = w1@w2 [256][4] and bias = b2 + b1@w2 [4]
__device__ float g_wf[C_ * 4];
__device__ float g_bias[4];

// ---------------------------------------------------------------------------
// Precompute (once): warp-cooperative. One warp per c-row: lane l covers
// j = l, l+32, l+64, l+96 (scalar w1 + float4 w2 each), 16 FMAs, then 4
// butterfly reductions. 32 blocks x 8 warps = 256 warps.
// ---------------------------------------------------------------------------
__global__ __launch_bounds__(256)
void wf_kernel(const float* __restrict__ w1, const float* __restrict__ b1,
               const float* __restrict__ w2, const float* __restrict__ b2) {
    const int warp = threadIdx.x >> 5;
    const int lane = threadIdx.x & 31;
    const int c    = blockIdx.x * 8 + warp;   // 0..255

    float acc0 = 0.f, acc1 = 0.f, acc2 = 0.f, acc3 = 0.f;
    #pragma unroll
    for (int k = 0; k < 4; k++) {
        const int j = lane + 32 * k;
        const float a = w1[c * 128 + j];
        const float4 wr = *reinterpret_cast<const float4*>(w2 + j * 4);
        acc0 = fmaf(a, wr.x, acc0);
        acc1 = fmaf(a, wr.y, acc1);
        acc2 = fmaf(a, wr.z, acc2);
        acc3 = fmaf(a, wr.w, acc3);
    }
    #pragma unroll
    for (int d = 16; d >= 1; d >>= 1) {
        acc0 += __shfl_xor_sync(0xffffffffu, acc0, d);
        acc1 += __shfl_xor_sync(0xffffffffu, acc1, d);
        acc2 += __shfl_xor_sync(0xffffffffu, acc2, d);
        acc3 += __shfl_xor_sync(0xffffffffu, acc3, d);
    }
    if (lane == 0)
        *reinterpret_cast<float4*>(g_wf + c * 4) = make_float4(acc0, acc1, acc2, acc3);

    // bias = b2 + b1 @ w2, computed by block 0 / warp 0 cooperatively
    if (blockIdx.x == 0 && warp == 0) {
        float s0 = 0.f, s1 = 0.f, s2 = 0.f, s3 = 0.f;
        #pragma unroll
        for (int k = 0; k < 4; k++) {
            const int j = lane + 32 * k;
            const float bv = b1[j];
            const float4 wr = *reinterpret_cast<const float4*>(w2 + j * 4);
            s0 = fmaf(bv, wr.x, s0);
            s1 = fmaf(bv, wr.y, s1);
            s2 = fmaf(bv, wr.z, s2);
            s3 = fmaf(bv, wr.w, s3);
        }
        #pragma unroll
        for (int d = 16; d >= 1; d >>= 1) {
            s0 += __shfl_xor_sync(0xffffffffu, s0, d);
            s1 += __shfl_xor_sync(0xffffffffu, s1, d);
            s2 += __shfl_xor_sync(0xffffffffu, s2, d);
            s3 += __shfl_xor_sync(0xffffffffu, s3, d);
        }
        if (lane == 0) {
            g_bias[0] = s0 + b2[0];
            g_bias[1] = s1 + b2[1];
            g_bias[2] = s2 + b2[2];
            g_bias[3] = s3 + b2[3];
        }
    }
}

// ---------------------------------------------------------------------------
// Phase 1: per-tile segmented max, accumulator [cquad][id][4ch]; one LDS.128
// snapshots 4 channels' maxima for a pixel's id. Non-negative float bits
// (init 0 == clamp at 0; int cmp == float cmp). Stale snapshots safe (monotone).
// Software-pipelined: next 8-channel batch loads issue before current batch's
// shared-memory work.
// ---------------------------------------------------------------------------
__global__ __launch_bounds__(THREADS1)
void seg_pool_kernel(const float* __restrict__ enc, const int* __restrict__ masks) {
    __shared__ int4 accum4[NQ * 33];            // 33 KB
    int* accum = reinterpret_cast<int*>(accum4);

    const int blk  = blockIdx.x;
    const int b    = blk / TILES_PER_B;
    const int tile = blk % TILES_PER_B;
    const int tid  = threadIdx.x;

    #pragma unroll
    for (int i = tid; i < NQ * 33 * 4; i += THREADS1) accum[i] = 0;

    const int pbase = tile * PT;
    const int4 idv = reinterpret_cast<const int4*>(masks + (size_t)b * P_ + pbase)[tid];
    const int id0 = idv.x, id1 = idv.y, id2 = idv.z, id3 = idv.w;

    __syncthreads();

    const float* encb = enc + (size_t)b * C_ * P_ + pbase;

    #define LOADV(DST, CBASE)                                                   \
        _Pragma("unroll")                                                       \
        for (int u = 0; u < 8; u++)                                             \
            DST[u] = reinterpret_cast<const float4*>(encb + (size_t)((CBASE) + u) * P_)[tid];

    #define CHECK_PIXEL(CQ, IDX, W0, W1, W2, W3, COMP)                          \
    {                                                                           \
        const int4 cur = accum4[(CQ) * 33 + IDX];                               \
        const int base = ((CQ) * 33 + IDX) * 4; int a;                          \
        a = __float_as_int(W0.COMP); if (a > cur.x) atomicMax(&accum[base+0], a); \
        a = __float_as_int(W1.COMP); if (a > cur.y) atomicMax(&accum[base+1], a); \
        a = __float_as_int(W2.COMP); if (a > cur.z) atomicMax(&accum[base+2], a); \
        a = __float_as_int(W3.COMP); if (a > cur.w) atomicMax(&accum[base+3], a); \
    }

    #define PROCESS(SRC, CBASE)                                                 \
        _Pragma("unroll")                                                       \
        for (int q = 0; q < 2; q++) {                                           \
            const int cq = ((CBASE) >> 2) + q;                                  \
            const float4 p0 = SRC[4*q + 0], p1 = SRC[4*q + 1],                  \
                         p2 = SRC[4*q + 2], p3 = SRC[4*q + 3];                  \
            CHECK_PIXEL(cq, id0, p0, p1, p2, p3, x)                             \
            CHECK_PIXEL(cq, id1, p0, p1, p2, p3, y)                             \
            CHECK_PIXEL(cq, id2, p0, p1, p2, p3, z)                             \
            CHECK_PIXEL(cq, id3, p0, p1, p2, p3, w)                             \
        }

    float4 va[8], vb[8];
    LOADV(va, 0)
    #pragma unroll 1
    for (int c0 = 0; c0 < C_; c0 += 16) {
        LOADV(vb, c0 + 8)
        PROCESS(va, c0)
        if (c0 + 16 < C_) { LOADV(va, c0 + 16) }
        PROCESS(vb, c0 + 8)
    }
    #undef LOADV
    #undef PROCESS
    #undef CHECK_PIXEL

    __syncthreads();

    // flush to [b][seg][tile][c] (drop id 0 = background)
    #pragma unroll
    for (int i = tid; i < NSEG * C_; i += THREADS1) {
        const int s = i >> 8;
        const int c = i & 255;
        g_scratch[(((size_t)b * NSEG + s) * TILES_PER_B + tile) * C_ + c] =
            __int_as_float(accum[((c >> 2) * 33 + s + 1) * 4 + (c & 3)]);
    }
}

// ---------------------------------------------------------------------------
// Phase 2: max over 64 tile-partials per (b,seg), then one multiply by the
// precomputed fused weight + 4-warp tree sum + sigmoid. Pure bandwidth.
// ---------------------------------------------------------------------------
__global__ __launch_bounds__(1024)
void reduce_mlp_kernel(float* __restrict__ out) {
    __shared__ float part[16][C_];   // 16 KB
    __shared__ float mlp[4][C_];     // 4 KB

    const int blk = blockIdx.x;      // b*NSEG + n
    const int b   = blk / NSEG;
    const int n   = blk % NSEG;
    const int tid = threadIdx.x;
    const int c4    = (tid & 63) * 4;
    const int chunk = tid >> 6;         // 0..15, each owns 4 tiles
    const int c     = tid >> 2;         // 0..255
    const int o     = tid & 3;          // 0..3

    const float wf = g_wf[tid];         // Wf[c][o], coalesced

    const float* base = g_scratch
        + (((size_t)b * NSEG + n) * TILES_PER_B + (size_t)chunk * 4) * C_ + c4;
    float4 v[4];
    #pragma unroll
    for (int t = 0; t < 4; t++)
        v[t] = *reinterpret_cast<const float4*>(base + (size_t)t * C_);
    float4 m = v[0];
    #pragma unroll
    for (int t = 1; t < 4; t++) {
        m.x = fmaxf(m.x, v[t].x); m.y = fmaxf(m.y, v[t].y);
        m.z = fmaxf(m.z, v[t].z); m.w = fmaxf(m.w, v[t].w);
    }
    *reinterpret_cast<float4*>(&part[chunk][c4]) = m;
    __syncthreads();

    #pragma unroll
    for (int stride = 8; stride >= 1; stride >>= 1) {
        if (chunk < stride) {
            float4 a = *reinterpret_cast<const float4*>(&part[chunk][c4]);
            float4 bb = *reinterpret_cast<const float4*>(&part[chunk + stride][c4]);
            a.x = fmaxf(a.x, bb.x); a.y = fmaxf(a.y, bb.y);
            a.z = fmaxf(a.z, bb.z); a.w = fmaxf(a.w, bb.w);
            *reinterpret_cast<float4*>(&part[chunk][c4]) = a;
        }
        __syncthreads();
    }
    // part[0][0..255] == pooled

    mlp[o][c] = part[0][c] * wf;
    __syncthreads();

    const int wid = tid >> 5, lane = tid & 31;
    if (wid < 4) {
        float s = 0.0f;
        #pragma unroll
        for (int k = 0; k < 8; k++) s += mlp[wid][lane + 32 * k];
        #pragma unroll
        for (int d = 16; d >= 1; d >>= 1) s += __shfl_xor_sync(0xffffffffu, s, d);
        if (lane == 0)
            out[blk * 4 + wid] = 1.0f / (1.0f + expf(-(s + g_bias[wid])));
    }
}

// ---------------------------------------------------------------------------
extern "C" void kernel_launch(void* const* d_in, const int* in_sizes, int n_in,
                              void* d_out, int out_size) {
    const float* enc   = (const float*)d_in[0];  // [4,256,256,256] f32
    const float* w1    = (const float*)d_in[1];  // [256,128]
    const float* b1    = (const float*)d_in[2];  // [128]
    const float* w2    = (const float*)d_in[3];  // [128,4]
    const float* b2    = (const float*)d_in[4];  // [4]
    const int*   masks = (const int*)d_in[5];    // [4,1,256,256] i32

    wf_kernel<<<32, 256>>>(w1, b1, w2, b2);
    seg_pool_kernel<<<NBLK1, THREADS1>>>(enc, masks);
    reduce_mlp_kernel<<<B_ * NSEG, 1024>>>((float*)d_out);
}